// round 13
// baseline (speedup 1.0000x reference)
#include <cuda_runtime.h>
#include <cuda_bf16.h>
#include <cuda_fp16.h>
#include <cstdint>

// ---------------------------------------------------------------------------
// Attention block on GB300 (sm_103 target — tcgen05 unavailable in harness):
//   x -(fp16 2-term HMMA, fused fp16-split epilogue)-> qkv(fp16 hi/lo)
//     -(fp16 HMMA flash attention: Q 2-term, K 1-term, P 1-term, V 2-term)
//     -> a(fp16 hi/lo) -(fp16 2-term HMMA)-> out (fp32)
// ---------------------------------------------------------------------------

#define M_ROWS 8192
#define N_EMB  1024
#define N_QKV  3072
#define SEQ_T  2048
#define NHEAD  16
#define HS     64
#define KDIM   1024

// Scratch (__device__ globals per allocation-free rule)
__device__ __half g_qkvhi[(size_t)M_ROWS * N_QKV];  // 48 MB
__device__ __half g_qkvlo[(size_t)M_ROWS * N_QKV];  // 48 MB
__device__ __half g_xh[(size_t)M_ROWS * KDIM];
__device__ __half g_xl[(size_t)M_ROWS * KDIM];
__device__ __half g_ah[(size_t)M_ROWS * KDIM];   // attention output hi
__device__ __half g_al[(size_t)M_ROWS * KDIM];   // attention output lo
__device__ __half g_wqh[(size_t)N_QKV * KDIM];   // Wqkv^T fp16
__device__ __half g_woh[(size_t)N_EMB * KDIM];   // Wout^T fp16

// ---------------------------------------------------------------------------
// PTX helpers (sm_80-portable subset: ldmatrix / mma.sync / cp.async)
// ---------------------------------------------------------------------------
__device__ __forceinline__ uint32_t smem_u32(const void* p) {
    uint32_t a;
    asm("{ .reg .u64 t; cvta.to.shared.u64 t, %1; cvt.u32.u64 %0, t; }"
        : "=r"(a) : "l"(p));
    return a;
}
__device__ __forceinline__ uint32_t swz(uint32_t o) { return o ^ ((o >> 3) & 0x70); }

__device__ __forceinline__ void cp16(uint32_t dst, const void* src) {
    asm volatile("cp.async.cg.shared.global [%0], [%1], 16;" :: "r"(dst), "l"(src));
}
__device__ __forceinline__ void cp_commit() {
    asm volatile("cp.async.commit_group;" ::: "memory");
}
__device__ __forceinline__ void cp_wait1() {
    asm volatile("cp.async.wait_group 1;" ::: "memory");
}
__device__ __forceinline__ void cp_wait0() {
    asm volatile("cp.async.wait_group 0;" ::: "memory");
}

__device__ __forceinline__ void ldsm4(uint32_t& r0, uint32_t& r1, uint32_t& r2,
                                      uint32_t& r3, uint32_t addr) {
    asm volatile("ldmatrix.sync.aligned.m8n8.x4.shared.b16 {%0,%1,%2,%3}, [%4];"
                 : "=r"(r0), "=r"(r1), "=r"(r2), "=r"(r3) : "r"(addr));
}
__device__ __forceinline__ void ldsm4t(uint32_t& r0, uint32_t& r1, uint32_t& r2,
                                       uint32_t& r3, uint32_t addr) {
    asm volatile("ldmatrix.sync.aligned.m8n8.x4.trans.shared.b16 {%0,%1,%2,%3}, [%4];"
                 : "=r"(r0), "=r"(r1), "=r"(r2), "=r"(r3) : "r"(addr));
}

// fp16 MMA
__device__ __forceinline__ void mma16816h(float* d, uint32_t a0, uint32_t a1,
                                          uint32_t a2, uint32_t a3,
                                          uint32_t b0, uint32_t b1) {
    asm volatile(
        "mma.sync.aligned.m16n8k16.row.col.f32.f16.f16.f32 "
        "{%0,%1,%2,%3}, {%4,%5,%6,%7}, {%8,%9}, {%0,%1,%2,%3};"
        : "+f"(d[0]), "+f"(d[1]), "+f"(d[2]), "+f"(d[3])
        : "r"(a0), "r"(a1), "r"(a2), "r"(a3), "r"(b0), "r"(b1));
}

__device__ __forceinline__ uint32_t packh(float a, float b) {
    __half2 t = __floats2half2_rn(a, b);
    return *reinterpret_cast<uint32_t*>(&t);
}

// ---------------------------------------------------------------------------
// 2-term fp16 HMMA GEMM: C[M,N] = (Ah+Al)[M,K] @ Bh[N,K]^T + bias
// Tile 128x128, K-chunks of 64, 3-stage cp.async pipeline (load-before-compute)
// mode 0: write fp32 C.  mode 1: write fp16 hi/lo split (Chi, Clo).
// ---------------------------------------------------------------------------
#define G2_TILE  16384                // 128x64 fp16 (SW128, 128B rows)
#define G2_STAGE (3 * G2_TILE)        // Ah, Al, Bh
#define G2_SMEM  (3 * G2_STAGE)       // 147456 B

__device__ __forceinline__ void load_chunk2(
    uint32_t stage, int k0,
    const __half* __restrict__ Ah, const __half* __restrict__ Al,
    const __half* __restrict__ Bh, int bm, int bn, int tid) {
    const __half* bases[3] = {Ah, Al, Bh};
    #pragma unroll
    for (int tile = 0; tile < 3; tile++) {
        const __half* base = bases[tile];
        int rowbase = (tile < 2) ? bm : bn;
        #pragma unroll
        for (int j = 0; j < 4; j++) {
            int p = tid + j * 256;
            int row = p >> 3, c16 = p & 7;
            cp16(stage + tile * G2_TILE + swz(row * 128 + c16 * 16),
                 base + (size_t)(rowbase + row) * KDIM + k0 + c16 * 8);
        }
    }
    cp_commit();
}

__global__ __launch_bounds__(256, 1)
void gemm2_h(const __half* __restrict__ Ah, const __half* __restrict__ Al,
             const __half* __restrict__ Bh, const float* __restrict__ bias,
             float* __restrict__ C32,
             __half* __restrict__ Chi, __half* __restrict__ Clo,
             int N, int mode) {
    extern __shared__ char smem[];
    uint32_t sb = smem_u32(smem);
    int tid = threadIdx.x, lane = tid & 31, w = tid >> 5;
    int bm = blockIdx.y * 128;
    int bn = blockIdx.x * 128;
    int wm = (w >> 2) * 64;
    int wn = (w & 3) * 32;

    float acc[4][4][4];
    #pragma unroll
    for (int i = 0; i < 4; i++)
        #pragma unroll
        for (int j = 0; j < 4; j++)
            #pragma unroll
            for (int r = 0; r < 4; r++) acc[i][j][r] = 0.f;

    int a_row = wm + (lane & 15);
    int a_hi8 = lane >> 4;
    int b_row = wn + (lane & 7) + ((lane >> 4) << 3);
    int b_hi8 = (lane >> 3) & 1;

    load_chunk2(sb, 0,  Ah, Al, Bh, bm, bn, tid);
    load_chunk2(sb + G2_STAGE, 64, Ah, Al, Bh, bm, bn, tid);

    #pragma unroll 1
    for (int c = 0; c < 16; c++) {
        uint32_t stage = sb + (uint32_t)(c % 3) * G2_STAGE;
        if (c < 15) cp_wait1(); else cp_wait0();
        __syncthreads();
        if (c + 2 < 16)
            load_chunk2(sb + (uint32_t)((c + 2) % 3) * G2_STAGE, (c + 2) * 64,
                        Ah, Al, Bh, bm, bn, tid);

        uint32_t tAh = stage, tAl = stage + G2_TILE, tBh = stage + 2 * G2_TILE;

        #pragma unroll
        for (int ks = 0; ks < 4; ks++) {
            uint32_t ah[4][4], al[4][4], bh[2][4];
            uint32_t ac16 = (uint32_t)(ks * 2 + a_hi8) * 16;
            uint32_t bc16 = (uint32_t)(ks * 2 + b_hi8) * 16;
            #pragma unroll
            for (int mt = 0; mt < 4; mt++) {
                uint32_t off = swz((uint32_t)(a_row + mt * 16) * 128 + ac16);
                ldsm4(ah[mt][0], ah[mt][1], ah[mt][2], ah[mt][3], tAh + off);
                ldsm4(al[mt][0], al[mt][1], al[mt][2], al[mt][3], tAl + off);
            }
            #pragma unroll
            for (int nt = 0; nt < 2; nt++) {
                uint32_t off = swz((uint32_t)(b_row + nt * 16) * 128 + bc16);
                ldsm4(bh[nt][0], bh[nt][1], bh[nt][2], bh[nt][3], tBh + off);
            }
            #pragma unroll
            for (int mt = 0; mt < 4; mt++) {
                #pragma unroll
                for (int n8 = 0; n8 < 4; n8++) {
                    uint32_t b0 = bh[n8 >> 1][(n8 & 1) * 2];
                    uint32_t b1 = bh[n8 >> 1][(n8 & 1) * 2 + 1];
                    mma16816h(acc[mt][n8], ah[mt][0], ah[mt][1], ah[mt][2], ah[mt][3], b0, b1);
                    mma16816h(acc[mt][n8], al[mt][0], al[mt][1], al[mt][2], al[mt][3], b0, b1);
                }
            }
        }
    }

    int tr = lane >> 2;
    int tc = (lane & 3) * 2;
    if (mode == 0) {
        #pragma unroll
        for (int mt = 0; mt < 4; mt++) {
            #pragma unroll
            for (int n8 = 0; n8 < 4; n8++) {
                int row0 = bm + wm + mt * 16 + tr;
                int col  = bn + wn + n8 * 8 + tc;
                float b0 = bias[col], b1 = bias[col + 1];
                float* p0 = C32 + (size_t)row0 * N + col;
                p0[0] = acc[mt][n8][0] + b0;
                p0[1] = acc[mt][n8][1] + b1;
                float* p1 = C32 + (size_t)(row0 + 8) * N + col;
                p1[0] = acc[mt][n8][2] + b0;
                p1[1] = acc[mt][n8][3] + b1;
            }
        }
    } else {
        #pragma unroll
        for (int mt = 0; mt < 4; mt++) {
            #pragma unroll
            for (int n8 = 0; n8 < 4; n8++) {
                int row0 = bm + wm + mt * 16 + tr;
                int col  = bn + wn + n8 * 8 + tc;
                float b0 = bias[col], b1 = bias[col + 1];
                float cv[2][2] = {{acc[mt][n8][0] + b0, acc[mt][n8][1] + b1},
                                  {acc[mt][n8][2] + b0, acc[mt][n8][3] + b1}};
                #pragma unroll
                for (int rr = 0; rr < 2; rr++) {
                    __half h0 = __float2half_rn(cv[rr][0]);
                    __half h1 = __float2half_rn(cv[rr][1]);
                    __half l0 = __float2half_rn(cv[rr][0] - __half2float(h0));
                    __half l1 = __float2half_rn(cv[rr][1] - __half2float(h1));
                    size_t o = ((size_t)(row0 + rr * 8) * N + col);
                    *reinterpret_cast<__half2*>(Chi + o) = __halves2half2(h0, h1);
                    *reinterpret_cast<__half2*>(Clo + o) = __halves2half2(l0, l1);
                }
            }
        }
    }
}

// ---------------------------------------------------------------------------
// fp32 -> fp16 hi/lo split (for x)
// ---------------------------------------------------------------------------
__global__ void split_f32_h(const float* __restrict__ in, __half* __restrict__ hi,
                            __half* __restrict__ lo, int n4) {
    int i = blockIdx.x * blockDim.x + threadIdx.x;
    if (i >= n4) return;
    float4 v = reinterpret_cast<const float4*>(in)[i];
    float vv[4] = {v.x, v.y, v.z, v.w};
    __half h[4], l[4];
    #pragma unroll
    for (int j = 0; j < 4; j++) {
        h[j] = __float2half_rn(vv[j]);
        l[j] = __float2half_rn(vv[j] - __half2float(h[j]));
    }
    reinterpret_cast<__half2*>(hi)[i * 2 + 0] = __halves2half2(h[0], h[1]);
    reinterpret_cast<__half2*>(hi)[i * 2 + 1] = __halves2half2(h[2], h[3]);
    reinterpret_cast<__half2*>(lo)[i * 2 + 0] = __halves2half2(l[0], l[1]);
    reinterpret_cast<__half2*>(lo)[i * 2 + 1] = __halves2half2(l[2], l[3]);
}

// ---------------------------------------------------------------------------
// W [K,N] fp32 -> Wt [N,K] fp16 (transpose + convert)
// ---------------------------------------------------------------------------
__global__ void transpose_cvt_h(const float* __restrict__ W, __half* __restrict__ Wt,
                                int K, int N) {
    __shared__ float t[32][33];
    int bn = blockIdx.x * 32, bk = blockIdx.y * 32;
    int tx = threadIdx.x, ty = threadIdx.y;
    #pragma unroll
    for (int r = 0; r < 32; r += 8)
        t[ty + r][tx] = W[(size_t)(bk + ty + r) * N + bn + tx];
    __syncthreads();
    #pragma unroll
    for (int r = 0; r < 32; r += 8)
        Wt[(size_t)(bn + ty + r) * K + bk + tx] = __float2half_rn(t[tx][ty + r]);
}

// ---------------------------------------------------------------------------
// Flash attention via fp16 HMMA: S = (qh+ql)·kh  (2 MMAs), O += p̂·(vh+vl) (2 MMAs).
// Block: 256 thr = 8 warps, 128 q rows. Key tiles of 64, 3-stage pipeline.
// Stage (24 KB): Kh@0, Vh@8K, Vl@16K. Heavy q-tiles scheduled first.
// ---------------------------------------------------------------------------
#define A_STAGE 24576
#define A_SMEM  (3 * A_STAGE)        // 73728 B

__device__ __forceinline__ void attn_load_kv(uint32_t stage, int k0,
        const __half* __restrict__ Hhi, const __half* __restrict__ Hlo,
        int h, int tid) {
    #pragma unroll
    for (int i = 0; i < 2; i++) {
        int p = tid + i * 256;          // 0..511
        int row = p >> 3, c = p & 7;
        size_t gk = (size_t)(k0 + row) * N_QKV +     N_EMB + h * HS + c * 8;
        size_t gv = (size_t)(k0 + row) * N_QKV + 2 * N_EMB + h * HS + c * 8;
        uint32_t so = swz(row * 128 + c * 16);
        cp16(stage + so,         Hhi + gk);   // K hi only
        cp16(stage + 8192 + so,  Hhi + gv);   // V hi
        cp16(stage + 16384 + so, Hlo + gv);   // V lo
    }
    cp_commit();
}

__global__ __launch_bounds__(256, 1)
void attn_mma(const __half* __restrict__ QKVhi,
              const __half* __restrict__ QKVlo,
              __half* __restrict__ Ohi, __half* __restrict__ Olo) {
    extern __shared__ char smem[];
    uint32_t sb = smem_u32(smem);
    int tid = threadIdx.x, lane = tid & 31, w = tid >> 5;
    int qb = gridDim.x - 1 - blockIdx.x;    // heavy (late) q-tiles first
    int bh = blockIdx.y, b = bh >> 4, h = bh & 15;
    const __half* Hhi = QKVhi + (size_t)b * SEQ_T * N_QKV;
    const __half* Hlo = QKVlo + (size_t)b * SEQ_T * N_QKV;
    int tr = lane >> 2, tc = lane & 3;
    int wrow0 = qb * 128 + w * 16;

    // ---- Stage Q tile (128x64 hi/lo) into smem, extract frags ----
    #pragma unroll
    for (int i = 0; i < 4; i++) {
        int p = tid + i * 256;
        int row = p >> 3, c = p & 7;
        size_t g = (size_t)(qb * 128 + row) * N_QKV + h * HS + c * 8;
        uint32_t so = swz(row * 128 + c * 16);
        cp16(sb + so, Hhi + g);
        cp16(sb + 16384 + so, Hlo + g);
    }
    cp_commit(); cp_wait0(); __syncthreads();

    uint32_t qh[4][4], ql[4][4];
    {
        int a_row = w * 16 + (lane & 15);
        int a_hi8 = lane >> 4;
        #pragma unroll
        for (int ks = 0; ks < 4; ks++) {
            uint32_t off = swz((uint32_t)a_row * 128 + (ks * 2 + a_hi8) * 16);
            ldsm4(qh[ks][0], qh[ks][1], qh[ks][2], qh[ks][3], sb + off);
            ldsm4(ql[ks][0], ql[ks][1], ql[ks][2], ql[ks][3], sb + 16384 + off);
        }
    }
    __syncthreads();

    // ---- Main loop over 64-key tiles (3-stage, load-before-compute) ----
    float m0 = -1e30f, m1 = -1e30f, l0 = 0.f, l1 = 0.f;
    float o[8][4];
    #pragma unroll
    for (int i = 0; i < 8; i++)
        #pragma unroll
        for (int r = 0; r < 4; r++) o[i][r] = 0.f;

    int ntiles = 2 * (qb + 1);
    int wmax = wrow0 + 15;

    attn_load_kv(sb, 0, Hhi, Hlo, h, tid);
    if (ntiles > 1) attn_load_kv(sb + A_STAGE, 64, Hhi, Hlo, h, tid);
    else cp_commit();   // keep group-count arithmetic uniform

    int b_row = (lane & 7) + ((lane >> 4) << 3);
    int b_hi8 = (lane >> 3) & 1;

    #pragma unroll 1
    for (int t = 0; t < ntiles; t++) {
        int k0 = t * 64;
        uint32_t stage = sb + (uint32_t)(t % 3) * A_STAGE;
        if (t + 1 < ntiles) cp_wait1(); else cp_wait0();
        __syncthreads();
        if (t + 2 < ntiles)
            attn_load_kv(sb + (uint32_t)((t + 2) % 3) * A_STAGE, (t + 2) * 64,
                         Hhi, Hlo, h, tid);

        if (k0 <= wmax) {   // warp-uniform: skip fully-masked tiles
            // ---- S = (qh+ql) · kh ----
            float s[8][4];
            #pragma unroll
            for (int i = 0; i < 8; i++)
                #pragma unroll
                for (int r = 0; r < 4; r++) s[i][r] = 0.f;

            #pragma unroll
            for (int ks = 0; ks < 4; ks++) {
                uint32_t kh[4][4];
                uint32_t bc16 = (uint32_t)(ks * 2 + b_hi8) * 16;
                #pragma unroll
                for (int nt = 0; nt < 4; nt++) {
                    uint32_t off = swz((uint32_t)(b_row + nt * 16) * 128 + bc16);
                    ldsm4(kh[nt][0], kh[nt][1], kh[nt][2], kh[nt][3], stage + off);
                }
                #pragma unroll
                for (int n8 = 0; n8 < 8; n8++) {
                    uint32_t b0 = kh[n8 >> 1][(n8 & 1) * 2];
                    uint32_t b1 = kh[n8 >> 1][(n8 & 1) * 2 + 1];
                    mma16816h(s[n8], qh[ks][0], qh[ks][1], qh[ks][2], qh[ks][3], b0, b1);
                    mma16816h(s[n8], ql[ks][0], ql[ks][1], ql[ks][2], ql[ks][3], b0, b1);
                }
            }

            // ---- scale + causal mask + row max ----
            int row0 = wrow0 + tr, row1 = row0 + 8;
            bool diag = (k0 + 63 > wrow0);
            float mx0 = -1e30f, mx1 = -1e30f;
            #pragma unroll
            for (int n8 = 0; n8 < 8; n8++) {
                #pragma unroll
                for (int r = 0; r < 4; r++) s[n8][r] *= 0.125f;
                if (diag) {
                    int c0 = k0 + n8 * 8 + tc * 2, c1 = c0 + 1;
                    if (c0 > row0) s[n8][0] = -3.0e38f;
                    if (c1 > row0) s[n8][1] = -3.0e38f;
                    if (c0 > row1) s[n8][2] = -3.0e38f;
                    if (c1 > row1) s[n8][3] = -3.0e38f;
                }
                mx0 = fmaxf(mx0, fmaxf(s[n8][0], s[n8][1]));
                mx1 = fmaxf(mx1, fmaxf(s[n8][2], s[n8][3]));
            }
            mx0 = fmaxf(mx0, __shfl_xor_sync(0xffffffffu, mx0, 1));
            mx0 = fmaxf(mx0, __shfl_xor_sync(0xffffffffu, mx0, 2));
            mx1 = fmaxf(mx1, __shfl_xor_sync(0xffffffffu, mx1, 1));
            mx1 = fmaxf(mx1, __shfl_xor_sync(0xffffffffu, mx1, 2));

            float nm0 = fmaxf(m0, mx0), nm1 = fmaxf(m1, mx1);
            float cr0 = __expf(m0 - nm0), cr1 = __expf(m1 - nm1);
            m0 = nm0; m1 = nm1;
            l0 *= cr0; l1 *= cr1;
            #pragma unroll
            for (int n8 = 0; n8 < 8; n8++) {
                o[n8][0] *= cr0; o[n8][1] *= cr0;
                o[n8][2] *= cr1; o[n8][3] *= cr1;
            }

            // ---- P = exp(S - m), single fp16 A-frag ----
            uint32_t ph[4][4];
            #pragma unroll
            for (int n8 = 0; n8 < 8; n8++) {
                float p0 = __expf(s[n8][0] - nm0);
                float p1 = __expf(s[n8][1] - nm0);
                float p2 = __expf(s[n8][2] - nm1);
                float p3 = __expf(s[n8][3] - nm1);
                l0 += p0 + p1; l1 += p2 + p3;
                int ks = n8 >> 1, half = (n8 & 1) * 2;
                ph[ks][half]     = packh(p0, p1);
                ph[ks][half + 1] = packh(p2, p3);
            }

            // ---- O += p̂ · (vh + vl); V via ldmatrix.trans ----
            #pragma unroll
            for (int ks = 0; ks < 4; ks++) {
                int v_row = ks * 16 + (lane & 7) + ((lane >> 3) & 1) * 8;
                #pragma unroll
                for (int np = 0; np < 4; np++) {
                    int hs0 = np * 16 + (lane >> 4) * 8;
                    uint32_t off = swz((uint32_t)v_row * 128 + hs0 * 2);
                    uint32_t v0, v1, v2, v3, u0, u1, u2, u3;
                    ldsm4t(v0, v1, v2, v3, stage + 8192 + off);
                    ldsm4t(u0, u1, u2, u3, stage + 16384 + off);
                    mma16816h(o[np * 2],     ph[ks][0], ph[ks][1], ph[ks][2], ph[ks][3], v0, v1);
                    mma16816h(o[np * 2],     ph[ks][0], ph[ks][1], ph[ks][2], ph[ks][3], u0, u1);
                    mma16816h(o[np * 2 + 1], ph[ks][0], ph[ks][1], ph[ks][2], ph[ks][3], v2, v3);
                    mma16816h(o[np * 2 + 1], ph[ks][0], ph[ks][1], ph[ks][2], ph[ks][3], u2, u3);
                }
            }
        }
    }

    // ---- finalize: reduce l, normalize, write fp16 hi/lo ----
    l0 += __shfl_xor_sync(0xffffffffu, l0, 1);
    l0 += __shfl_xor_sync(0xffffffffu, l0, 2);
    l1 += __shfl_xor_sync(0xffffffffu, l1, 1);
    l1 += __shfl_xor_sync(0xffffffffu, l1, 2);
    float i0 = 1.f / l0, i1 = 1.f / l1;

    size_t o0 = (size_t)(b * SEQ_T + wrow0 + tr) * N_EMB + h * HS + tc * 2;
    size_t o1 = (size_t)(b * SEQ_T + wrow0 + tr + 8) * N_EMB + h * HS + tc * 2;
    #pragma unroll
    for (int n8 = 0; n8 < 8; n8++) {
        float v0 = o[n8][0] * i0, v1 = o[n8][1] * i0;
        float v2 = o[n8][2] * i1, v3 = o[n8][3] * i1;
        __half h0 = __float2half_rn(v0), h1 = __float2half_rn(v1);
        __half h2 = __float2half_rn(v2), h3 = __float2half_rn(v3);
        __half e0 = __float2half_rn(v0 - __half2float(h0));
        __half e1 = __float2half_rn(v1 - __half2float(h1));
        __half e2 = __float2half_rn(v2 - __half2float(h2));
        __half e3 = __float2half_rn(v3 - __half2float(h3));
        *reinterpret_cast<__half2*>(Ohi + o0 + n8 * 8) = __halves2half2(h0, h1);
        *reinterpret_cast<__half2*>(Olo + o0 + n8 * 8) = __halves2half2(e0, e1);
        *reinterpret_cast<__half2*>(Ohi + o1 + n8 * 8) = __halves2half2(h2, h3);
        *reinterpret_cast<__half2*>(Olo + o1 + n8 * 8) = __halves2half2(e2, e3);
    }
}

// ---------------------------------------------------------------------------
// Launch
// ---------------------------------------------------------------------------
extern "C" void kernel_launch(void* const* d_in, const int* in_sizes, int n_in,
                              void* d_out, int out_size) {
    const float* x    = (const float*)d_in[0];
    const float* Wqkv = (const float*)d_in[1];
    const float* bqkv = (const float*)d_in[2];
    const float* Wout = (const float*)d_in[3];
    const float* bout = (const float*)d_in[4];
    float* out = (float*)d_out;

    __half *qkvhi, *qkvlo, *xh, *xl, *ah, *al, *wqh, *woh;
    cudaGetSymbolAddress((void**)&qkvhi, g_qkvhi);
    cudaGetSymbolAddress((void**)&qkvlo, g_qkvlo);
    cudaGetSymbolAddress((void**)&xh,  g_xh);
    cudaGetSymbolAddress((void**)&xl,  g_xl);
    cudaGetSymbolAddress((void**)&ah,  g_ah);
    cudaGetSymbolAddress((void**)&al,  g_al);
    cudaGetSymbolAddress((void**)&wqh, g_wqh);
    cudaGetSymbolAddress((void**)&woh, g_woh);

    cudaFuncSetAttribute(gemm2_h, cudaFuncAttributeMaxDynamicSharedMemorySize, G2_SMEM);
    cudaFuncSetAttribute(attn_mma, cudaFuncAttributeMaxDynamicSharedMemorySize, A_SMEM);

    int n4x = (M_ROWS * KDIM) / 4;

    // Precompute operands
    split_f32_h<<<(n4x + 255) / 256, 256>>>(x, xh, xl, n4x);
    transpose_cvt_h<<<dim3(N_QKV / 32, KDIM / 32), dim3(32, 8)>>>(Wqkv, wqh, KDIM, N_QKV);
    transpose_cvt_h<<<dim3(N_EMB / 32, KDIM / 32), dim3(32, 8)>>>(Wout, woh, KDIM, N_EMB);

    // 1) QKV projection (fp16 2-term), fused fp16 hi/lo split epilogue
    gemm2_h<<<dim3(N_QKV / 128, M_ROWS / 128), 256, G2_SMEM>>>(
        xh, xl, wqh, bqkv, nullptr, qkvhi, qkvlo, N_QKV, 1);

    // 2) Flash attention (fp16), fused fp16 hi/lo split epilogue
    attn_mma<<<dim3(SEQ_T / 128, 4 * NHEAD), 256, A_SMEM>>>(qkvhi, qkvlo, ah, al);

    // 3) Output projection (fp16 2-term) -> fp32 out
    gemm2_h<<<dim3(N_EMB / 128, M_ROWS / 128), 256, G2_SMEM>>>(
        ah, al, woh, bout, out, nullptr, nullptr, N_EMB, 0);
}

// round 14
// speedup vs baseline: 1.7361x; 1.7361x over previous
#include <cuda_runtime.h>
#include <cuda_bf16.h>
#include <cuda_fp16.h>
#include <cstdint>

// ---------------------------------------------------------------------------
// Attention block on GB300 (sm_103 target — tcgen05 unavailable in harness):
//   x -(fp16 2-term HMMA)-> qkv(fp16 hi/lo)
//     -(fp16 HMMA flash attn: Q 2-term, K/P/V 1-term)-> a(fp16 hi/lo)
//     -(fp16 2-term HMMA)-> out (fp32)
// 2 CTAs/SM on gemm + attention (__launch_bounds__(256,2), low-reg loops).
// ---------------------------------------------------------------------------

#define M_ROWS 8192
#define N_EMB  1024
#define N_QKV  3072
#define SEQ_T  2048
#define NHEAD  16
#define HS     64
#define KDIM   1024

__device__ __half g_qkvhi[(size_t)M_ROWS * N_QKV];  // 48 MB
__device__ __half g_qkvlo[(size_t)M_ROWS * N_QKV];  // 48 MB
__device__ __half g_xh[(size_t)M_ROWS * KDIM];
__device__ __half g_xl[(size_t)M_ROWS * KDIM];
__device__ __half g_ah[(size_t)M_ROWS * KDIM];
__device__ __half g_al[(size_t)M_ROWS * KDIM];
__device__ __half g_wqh[(size_t)N_QKV * KDIM];
__device__ __half g_woh[(size_t)N_EMB * KDIM];

// ---------------------------------------------------------------------------
// PTX helpers
// ---------------------------------------------------------------------------
__device__ __forceinline__ uint32_t smem_u32(const void* p) {
    uint32_t a;
    asm("{ .reg .u64 t; cvta.to.shared.u64 t, %1; cvt.u32.u64 %0, t; }"
        : "=r"(a) : "l"(p));
    return a;
}
__device__ __forceinline__ uint32_t swz(uint32_t o) { return o ^ ((o >> 3) & 0x70); }

__device__ __forceinline__ void cp16(uint32_t dst, const void* src) {
    asm volatile("cp.async.cg.shared.global [%0], [%1], 16;" :: "r"(dst), "l"(src));
}
__device__ __forceinline__ void cp_commit() {
    asm volatile("cp.async.commit_group;" ::: "memory");
}
__device__ __forceinline__ void cp_wait1() {
    asm volatile("cp.async.wait_group 1;" ::: "memory");
}
__device__ __forceinline__ void cp_wait0() {
    asm volatile("cp.async.wait_group 0;" ::: "memory");
}

__device__ __forceinline__ void ldsm4(uint32_t& r0, uint32_t& r1, uint32_t& r2,
                                      uint32_t& r3, uint32_t addr) {
    asm volatile("ldmatrix.sync.aligned.m8n8.x4.shared.b16 {%0,%1,%2,%3}, [%4];"
                 : "=r"(r0), "=r"(r1), "=r"(r2), "=r"(r3) : "r"(addr));
}
__device__ __forceinline__ void ldsm4t(uint32_t& r0, uint32_t& r1, uint32_t& r2,
                                       uint32_t& r3, uint32_t addr) {
    asm volatile("ldmatrix.sync.aligned.m8n8.x4.trans.shared.b16 {%0,%1,%2,%3}, [%4];"
                 : "=r"(r0), "=r"(r1), "=r"(r2), "=r"(r3) : "r"(addr));
}

__device__ __forceinline__ void mma16816h(float* d, uint32_t a0, uint32_t a1,
                                          uint32_t a2, uint32_t a3,
                                          uint32_t b0, uint32_t b1) {
    asm volatile(
        "mma.sync.aligned.m16n8k16.row.col.f32.f16.f16.f32 "
        "{%0,%1,%2,%3}, {%4,%5,%6,%7}, {%8,%9}, {%0,%1,%2,%3};"
        : "+f"(d[0]), "+f"(d[1]), "+f"(d[2]), "+f"(d[3])
        : "r"(a0), "r"(a1), "r"(a2), "r"(a3), "r"(b0), "r"(b1));
}

__device__ __forceinline__ uint32_t packh(float a, float b) {
    __half2 t = __floats2half2_rn(a, b);
    return *reinterpret_cast<uint32_t*>(&t);
}

// ---------------------------------------------------------------------------
// 2-term fp16 HMMA GEMM: C[M,N] = (Ah+Al)[M,K] @ Bh[N,K]^T + bias
// Tile 128x128, K-chunks of 64, 2-stage pipeline, 2 CTAs/SM.
// mode 0: fp32 C.  mode 1: fp16 hi/lo split (Chi, Clo).
// ---------------------------------------------------------------------------
#define G2_TILE  16384                // 128x64 fp16 (SW128, 128B rows)
#define G2_STAGE (3 * G2_TILE)        // Ah, Al, Bh
#define G2_SMEM  (2 * G2_STAGE)       // 98304 B -> 2 CTAs/SM

__device__ __forceinline__ void load_chunk2(
    uint32_t stage, int k0,
    const __half* __restrict__ Ah, const __half* __restrict__ Al,
    const __half* __restrict__ Bh, int bm, int bn, int tid) {
    const __half* bases[3] = {Ah, Al, Bh};
    #pragma unroll
    for (int tile = 0; tile < 3; tile++) {
        const __half* base = bases[tile];
        int rowbase = (tile < 2) ? bm : bn;
        #pragma unroll
        for (int j = 0; j < 4; j++) {
            int p = tid + j * 256;
            int row = p >> 3, c16 = p & 7;
            cp16(stage + tile * G2_TILE + swz(row * 128 + c16 * 16),
                 base + (size_t)(rowbase + row) * KDIM + k0 + c16 * 8);
        }
    }
    cp_commit();
}

__global__ __launch_bounds__(256, 2)
void gemm2_h(const __half* __restrict__ Ah, const __half* __restrict__ Al,
             const __half* __restrict__ Bh, const float* __restrict__ bias,
             float* __restrict__ C32,
             __half* __restrict__ Chi, __half* __restrict__ Clo,
             int N, int mode) {
    extern __shared__ char smem[];
    uint32_t sb = smem_u32(smem);
    int tid = threadIdx.x, lane = tid & 31, w = tid >> 5;
    int bm = blockIdx.y * 128;
    int bn = blockIdx.x * 128;
    int wm = (w >> 2) * 64;
    int wn = (w & 3) * 32;

    float acc[4][4][4];
    #pragma unroll
    for (int i = 0; i < 4; i++)
        #pragma unroll
        for (int j = 0; j < 4; j++)
            #pragma unroll
            for (int r = 0; r < 4; r++) acc[i][j][r] = 0.f;

    int a_row = wm + (lane & 15);
    int a_hi8 = lane >> 4;
    int b_row = wn + (lane & 7) + ((lane >> 4) << 3);
    int b_hi8 = (lane >> 3) & 1;

    load_chunk2(sb, 0,  Ah, Al, Bh, bm, bn, tid);
    load_chunk2(sb + G2_STAGE, 64, Ah, Al, Bh, bm, bn, tid);

    #pragma unroll 1
    for (int c = 0; c < 16; c++) {
        uint32_t stage = sb + (uint32_t)(c & 1) * G2_STAGE;
        if (c < 15) cp_wait1(); else cp_wait0();
        __syncthreads();

        uint32_t tAh = stage, tAl = stage + G2_TILE, tBh = stage + 2 * G2_TILE;
        #pragma unroll
        for (int ks = 0; ks < 4; ks++) {
            uint32_t bh[2][4];
            uint32_t ac16 = (uint32_t)(ks * 2 + a_hi8) * 16;
            uint32_t bc16 = (uint32_t)(ks * 2 + b_hi8) * 16;
            #pragma unroll
            for (int nt = 0; nt < 2; nt++) {
                uint32_t off = swz((uint32_t)(b_row + nt * 16) * 128 + bc16);
                ldsm4(bh[nt][0], bh[nt][1], bh[nt][2], bh[nt][3], tBh + off);
            }
            #pragma unroll
            for (int mt = 0; mt < 4; mt++) {
                uint32_t ah[4], al[4];
                uint32_t off = swz((uint32_t)(a_row + mt * 16) * 128 + ac16);
                ldsm4(ah[0], ah[1], ah[2], ah[3], tAh + off);
                ldsm4(al[0], al[1], al[2], al[3], tAl + off);
                #pragma unroll
                for (int n8 = 0; n8 < 4; n8++) {
                    uint32_t b0 = bh[n8 >> 1][(n8 & 1) * 2];
                    uint32_t b1 = bh[n8 >> 1][(n8 & 1) * 2 + 1];
                    mma16816h(acc[mt][n8], ah[0], ah[1], ah[2], ah[3], b0, b1);
                    mma16816h(acc[mt][n8], al[0], al[1], al[2], al[3], b0, b1);
                }
            }
        }
        __syncthreads();
        if (c + 2 < 16)
            load_chunk2(stage, (c + 2) * 64, Ah, Al, Bh, bm, bn, tid);
    }

    int tr = lane >> 2;
    int tc = (lane & 3) * 2;
    if (mode == 0) {
        #pragma unroll
        for (int mt = 0; mt < 4; mt++) {
            #pragma unroll
            for (int n8 = 0; n8 < 4; n8++) {
                int row0 = bm + wm + mt * 16 + tr;
                int col  = bn + wn + n8 * 8 + tc;
                float b0 = bias[col], b1 = bias[col + 1];
                float* p0 = C32 + (size_t)row0 * N + col;
                p0[0] = acc[mt][n8][0] + b0;
                p0[1] = acc[mt][n8][1] + b1;
                float* p1 = C32 + (size_t)(row0 + 8) * N + col;
                p1[0] = acc[mt][n8][2] + b0;
                p1[1] = acc[mt][n8][3] + b1;
            }
        }
    } else {
        #pragma unroll
        for (int mt = 0; mt < 4; mt++) {
            #pragma unroll
            for (int n8 = 0; n8 < 4; n8++) {
                int row0 = bm + wm + mt * 16 + tr;
                int col  = bn + wn + n8 * 8 + tc;
                float b0 = bias[col], b1 = bias[col + 1];
                float cv[2][2] = {{acc[mt][n8][0] + b0, acc[mt][n8][1] + b1},
                                  {acc[mt][n8][2] + b0, acc[mt][n8][3] + b1}};
                #pragma unroll
                for (int rr = 0; rr < 2; rr++) {
                    __half h0 = __float2half_rn(cv[rr][0]);
                    __half h1 = __float2half_rn(cv[rr][1]);
                    __half l0 = __float2half_rn(cv[rr][0] - __half2float(h0));
                    __half l1 = __float2half_rn(cv[rr][1] - __half2float(h1));
                    size_t o = ((size_t)(row0 + rr * 8) * N + col);
                    *reinterpret_cast<__half2*>(Chi + o) = __halves2half2(h0, h1);
                    *reinterpret_cast<__half2*>(Clo + o) = __halves2half2(l0, l1);
                }
            }
        }
    }
}

// ---------------------------------------------------------------------------
// fp32 -> fp16 hi/lo split (for x)
// ---------------------------------------------------------------------------
__global__ void split_f32_h(const float* __restrict__ in, __half* __restrict__ hi,
                            __half* __restrict__ lo, int n4) {
    int i = blockIdx.x * blockDim.x + threadIdx.x;
    if (i >= n4) return;
    float4 v = reinterpret_cast<const float4*>(in)[i];
    float vv[4] = {v.x, v.y, v.z, v.w};
    __half h[4], l[4];
    #pragma unroll
    for (int j = 0; j < 4; j++) {
        h[j] = __float2half_rn(vv[j]);
        l[j] = __float2half_rn(vv[j] - __half2float(h[j]));
    }
    reinterpret_cast<__half2*>(hi)[i * 2 + 0] = __halves2half2(h[0], h[1]);
    reinterpret_cast<__half2*>(hi)[i * 2 + 1] = __halves2half2(h[2], h[3]);
    reinterpret_cast<__half2*>(lo)[i * 2 + 0] = __halves2half2(l[0], l[1]);
    reinterpret_cast<__half2*>(lo)[i * 2 + 1] = __halves2half2(l[2], l[3]);
}

// ---------------------------------------------------------------------------
// W [K,N] fp32 -> Wt [N,K] fp16 (transpose + convert)
// ---------------------------------------------------------------------------
__global__ void transpose_cvt_h(const float* __restrict__ W, __half* __restrict__ Wt,
                                int K, int N) {
    __shared__ float t[32][33];
    int bn = blockIdx.x * 32, bk = blockIdx.y * 32;
    int tx = threadIdx.x, ty = threadIdx.y;
    #pragma unroll
    for (int r = 0; r < 32; r += 8)
        t[ty + r][tx] = W[(size_t)(bk + ty + r) * N + bn + tx];
    __syncthreads();
    #pragma unroll
    for (int r = 0; r < 32; r += 8)
        Wt[(size_t)(bn + ty + r) * K + bk + tx] = __float2half_rn(t[tx][ty + r]);
}

// ---------------------------------------------------------------------------
// Flash attention fp16 HMMA: S = (qh+ql)·kh (2 MMAs), O += p̂·vh (1 MMA).
// Block 256 thr / 8 warps / 128 q rows; 64-key tiles; 3-stage 16KB pipeline.
// Stage: Kh@0, Vh@8K. Heavy q-tiles scheduled first. 2 CTAs/SM.
// ---------------------------------------------------------------------------
#define A_STAGE 16384
#define A_SMEM  (3 * A_STAGE)        // 49152 B

__device__ __forceinline__ void attn_load_kv(uint32_t stage, int k0,
        const __half* __restrict__ Hhi, int h, int tid) {
    #pragma unroll
    for (int i = 0; i < 2; i++) {
        int p = tid + i * 256;          // 0..511
        int row = p >> 3, c = p & 7;
        size_t gk = (size_t)(k0 + row) * N_QKV +     N_EMB + h * HS + c * 8;
        size_t gv = (size_t)(k0 + row) * N_QKV + 2 * N_EMB + h * HS + c * 8;
        uint32_t so = swz(row * 128 + c * 16);
        cp16(stage + so,        Hhi + gk);   // K hi
        cp16(stage + 8192 + so, Hhi + gv);   // V hi
    }
    cp_commit();
}

__global__ __launch_bounds__(256, 2)
void attn_mma(const __half* __restrict__ QKVhi,
              const __half* __restrict__ QKVlo,
              __half* __restrict__ Ohi, __half* __restrict__ Olo) {
    extern __shared__ char smem[];
    uint32_t sb = smem_u32(smem);
    int tid = threadIdx.x, lane = tid & 31, w = tid >> 5;
    int qb = gridDim.x - 1 - blockIdx.x;    // heavy (late) q-tiles first
    int bh = blockIdx.y, b = bh >> 4, h = bh & 15;
    const __half* Hhi = QKVhi + (size_t)b * SEQ_T * N_QKV;
    const __half* Hlo = QKVlo + (size_t)b * SEQ_T * N_QKV;
    int tr = lane >> 2, tc = lane & 3;
    int wrow0 = qb * 128 + w * 16;

    // ---- Stage Q tile (128x64 hi/lo) into smem, extract frags ----
    #pragma unroll
    for (int i = 0; i < 4; i++) {
        int p = tid + i * 256;
        int row = p >> 3, c = p & 7;
        size_t g = (size_t)(qb * 128 + row) * N_QKV + h * HS + c * 8;
        uint32_t so = swz(row * 128 + c * 16);
        cp16(sb + so, Hhi + g);
        cp16(sb + 16384 + so, Hlo + g);
    }
    cp_commit(); cp_wait0(); __syncthreads();

    uint32_t qh[4][4], ql[4][4];
    {
        int a_row = w * 16 + (lane & 15);
        int a_hi8 = lane >> 4;
        #pragma unroll
        for (int ks = 0; ks < 4; ks++) {
            uint32_t off = swz((uint32_t)a_row * 128 + (ks * 2 + a_hi8) * 16);
            ldsm4(qh[ks][0], qh[ks][1], qh[ks][2], qh[ks][3], sb + off);
            ldsm4(ql[ks][0], ql[ks][1], ql[ks][2], ql[ks][3], sb + 16384 + off);
        }
    }
    __syncthreads();

    // ---- Main loop over 64-key tiles ----
    float m0 = -1e30f, m1 = -1e30f, l0 = 0.f, l1 = 0.f;
    float o[8][4];
    #pragma unroll
    for (int i = 0; i < 8; i++)
        #pragma unroll
        for (int r = 0; r < 4; r++) o[i][r] = 0.f;

    int ntiles = 2 * (qb + 1);
    int wmax = wrow0 + 15;

    attn_load_kv(sb, 0, Hhi, h, tid);
    attn_load_kv(sb + A_STAGE, 64, Hhi, h, tid);

    int b_row = (lane & 7) + ((lane >> 4) << 3);
    int b_hi8 = (lane >> 3) & 1;

    #pragma unroll 1
    for (int t = 0; t < ntiles; t++) {
        int k0 = t * 64;
        uint32_t stage = sb + (uint32_t)(t % 3) * A_STAGE;
        if (t + 1 < ntiles) cp_wait1(); else cp_wait0();
        __syncthreads();
        if (t + 2 < ntiles)
            attn_load_kv(sb + (uint32_t)((t + 2) % 3) * A_STAGE, (t + 2) * 64,
                         Hhi, h, tid);

        if (k0 <= wmax) {   // warp-uniform: skip fully-masked tiles
            // ---- S = (qh+ql) · kh ----
            float s[8][4];
            #pragma unroll
            for (int i = 0; i < 8; i++)
                #pragma unroll
                for (int r = 0; r < 4; r++) s[i][r] = 0.f;

            #pragma unroll
            for (int ks = 0; ks < 4; ks++) {
                uint32_t bc16 = (uint32_t)(ks * 2 + b_hi8) * 16;
                #pragma unroll
                for (int nt = 0; nt < 4; nt++) {
                    uint32_t kh[4];
                    uint32_t off = swz((uint32_t)(b_row + nt * 16) * 128 + bc16);
                    ldsm4(kh[0], kh[1], kh[2], kh[3], stage + off);
                    #pragma unroll
                    for (int half = 0; half < 2; half++) {
                        int n8 = nt * 2 + half;
                        uint32_t b0 = kh[half * 2], b1 = kh[half * 2 + 1];
                        mma16816h(s[n8], qh[ks][0], qh[ks][1], qh[ks][2], qh[ks][3], b0, b1);
                        mma16816h(s[n8], ql[ks][0], ql[ks][1], ql[ks][2], ql[ks][3], b0, b1);
                    }
                }
            }

            // ---- scale + causal mask + row max ----
            int row0 = wrow0 + tr, row1 = row0 + 8;
            bool diag = (k0 + 63 > wrow0);
            float mx0 = -1e30f, mx1 = -1e30f;
            #pragma unroll
            for (int n8 = 0; n8 < 8; n8++) {
                #pragma unroll
                for (int r = 0; r < 4; r++) s[n8][r] *= 0.125f;
                if (diag) {
                    int c0 = k0 + n8 * 8 + tc * 2, c1 = c0 + 1;
                    if (c0 > row0) s[n8][0] = -3.0e38f;
                    if (c1 > row0) s[n8][1] = -3.0e38f;
                    if (c0 > row1) s[n8][2] = -3.0e38f;
                    if (c1 > row1) s[n8][3] = -3.0e38f;
                }
                mx0 = fmaxf(mx0, fmaxf(s[n8][0], s[n8][1]));
                mx1 = fmaxf(mx1, fmaxf(s[n8][2], s[n8][3]));
            }
            mx0 = fmaxf(mx0, __shfl_xor_sync(0xffffffffu, mx0, 1));
            mx0 = fmaxf(mx0, __shfl_xor_sync(0xffffffffu, mx0, 2));
            mx1 = fmaxf(mx1, __shfl_xor_sync(0xffffffffu, mx1, 1));
            mx1 = fmaxf(mx1, __shfl_xor_sync(0xffffffffu, mx1, 2));

            float nm0 = fmaxf(m0, mx0), nm1 = fmaxf(m1, mx1);
            float cr0 = __expf(m0 - nm0), cr1 = __expf(m1 - nm1);
            m0 = nm0; m1 = nm1;
            l0 *= cr0; l1 *= cr1;
            #pragma unroll
            for (int n8 = 0; n8 < 8; n8++) {
                o[n8][0] *= cr0; o[n8][1] *= cr0;
                o[n8][2] *= cr1; o[n8][3] *= cr1;
            }

            // ---- P = exp(S - m), single fp16 A-frag ----
            uint32_t ph[4][4];
            #pragma unroll
            for (int n8 = 0; n8 < 8; n8++) {
                float p0 = __expf(s[n8][0] - nm0);
                float p1 = __expf(s[n8][1] - nm0);
                float p2 = __expf(s[n8][2] - nm1);
                float p3 = __expf(s[n8][3] - nm1);
                l0 += p0 + p1; l1 += p2 + p3;
                int ks = n8 >> 1, half = (n8 & 1) * 2;
                ph[ks][half]     = packh(p0, p1);
                ph[ks][half + 1] = packh(p2, p3);
            }

            // ---- O += p̂ · vh; V via ldmatrix.trans ----
            #pragma unroll
            for (int ks = 0; ks < 4; ks++) {
                int v_row = ks * 16 + (lane & 7) + ((lane >> 3) & 1) * 8;
                #pragma unroll
                for (int np = 0; np < 4; np++) {
                    int hs0 = np * 16 + (lane >> 4) * 8;
                    uint32_t off = swz((uint32_t)v_row * 128 + hs0 * 2);
                    uint32_t v0, v1, v2, v3;
                    ldsm4t(v0, v1, v2, v3, stage + 8192 + off);
                    mma16816h(o[np * 2],     ph[ks][0], ph[ks][1], ph[ks][2], ph[ks][3], v0, v1);
                    mma16816h(o[np * 2 + 1], ph[ks][0], ph[ks][1], ph[ks][2], ph[ks][3], v2, v3);
                }
            }
        }
    }

    // ---- finalize: reduce l, normalize, write fp16 hi/lo ----
    l0 += __shfl_xor_sync(0xffffffffu, l0, 1);
    l0 += __shfl_xor_sync(0xffffffffu, l0, 2);
    l1 += __shfl_xor_sync(0xffffffffu, l1, 1);
    l1 += __shfl_xor_sync(0xffffffffu, l1, 2);
    float i0 = 1.f / l0, i1 = 1.f / l1;

    size_t o0 = (size_t)(b * SEQ_T + wrow0 + tr) * N_EMB + h * HS + tc * 2;
    size_t o1 = (size_t)(b * SEQ_T + wrow0 + tr + 8) * N_EMB + h * HS + tc * 2;
    #pragma unroll
    for (int n8 = 0; n8 < 8; n8++) {
        float v0 = o[n8][0] * i0, v1 = o[n8][1] * i0;
        float v2 = o[n8][2] * i1, v3 = o[n8][3] * i1;
        __half h0 = __float2half_rn(v0), h1 = __float2half_rn(v1);
        __half h2 = __float2half_rn(v2), h3 = __float2half_rn(v3);
        __half e0 = __float2half_rn(v0 - __half2float(h0));
        __half e1 = __float2half_rn(v1 - __half2float(h1));
        __half e2 = __float2half_rn(v2 - __half2float(h2));
        __half e3 = __float2half_rn(v3 - __half2float(h3));
        *reinterpret_cast<__half2*>(Ohi + o0 + n8 * 8) = __halves2half2(h0, h1);
        *reinterpret_cast<__half2*>(Olo + o0 + n8 * 8) = __halves2half2(e0, e1);
        *reinterpret_cast<__half2*>(Ohi + o1 + n8 * 8) = __halves2half2(h2, h3);
        *reinterpret_cast<__half2*>(Olo + o1 + n8 * 8) = __halves2half2(e2, e3);
    }
}

// ---------------------------------------------------------------------------
// Launch
// ---------------------------------------------------------------------------
extern "C" void kernel_launch(void* const* d_in, const int* in_sizes, int n_in,
                              void* d_out, int out_size) {
    const float* x    = (const float*)d_in[0];
    const float* Wqkv = (const float*)d_in[1];
    const float* bqkv = (const float*)d_in[2];
    const float* Wout = (const float*)d_in[3];
    const float* bout = (const float*)d_in[4];
    float* out = (float*)d_out;

    __half *qkvhi, *qkvlo, *xh, *xl, *ah, *al, *wqh, *woh;
    cudaGetSymbolAddress((void**)&qkvhi, g_qkvhi);
    cudaGetSymbolAddress((void**)&qkvlo, g_qkvlo);
    cudaGetSymbolAddress((void**)&xh,  g_xh);
    cudaGetSymbolAddress((void**)&xl,  g_xl);
    cudaGetSymbolAddress((void**)&ah,  g_ah);
    cudaGetSymbolAddress((void**)&al,  g_al);
    cudaGetSymbolAddress((void**)&wqh, g_wqh);
    cudaGetSymbolAddress((void**)&woh, g_woh);

    cudaFuncSetAttribute(gemm2_h, cudaFuncAttributeMaxDynamicSharedMemorySize, G2_SMEM);
    cudaFuncSetAttribute(attn_mma, cudaFuncAttributeMaxDynamicSharedMemorySize, A_SMEM);

    int n4x = (M_ROWS * KDIM) / 4;

    // Precompute operands
    split_f32_h<<<(n4x + 255) / 256, 256>>>(x, xh, xl, n4x);
    transpose_cvt_h<<<dim3(N_QKV / 32, KDIM / 32), dim3(32, 8)>>>(Wqkv, wqh, KDIM, N_QKV);
    transpose_cvt_h<<<dim3(N_EMB / 32, KDIM / 32), dim3(32, 8)>>>(Wout, woh, KDIM, N_EMB);

    // 1) QKV projection (fp16 2-term), fused fp16 hi/lo split epilogue
    gemm2_h<<<dim3(N_QKV / 128, M_ROWS / 128), 256, G2_SMEM>>>(
        xh, xl, wqh, bqkv, nullptr, qkvhi, qkvlo, N_QKV, 1);

    // 2) Flash attention (fp16), fused fp16 hi/lo split epilogue
    attn_mma<<<dim3(SEQ_T / 128, 4 * NHEAD), 256, A_SMEM>>>(qkvhi, qkvlo, ah, al);

    // 3) Output projection (fp16 2-term) -> fp32 out
    gemm2_h<<<dim3(N_EMB / 128, M_ROWS / 128), 256, G2_SMEM>>>(
        ah, al, woh, bout, out, nullptr, nullptr, N_EMB, 0);
}